// round 13
// baseline (speedup 1.0000x reference)
#include <cuda_runtime.h>
#include <cuda_bf16.h>
#include <math.h>
#include <stdint.h>

#define Bn 128
#define Tn 512
#define Dn 256
#define Vn 4096
#define Sn 512

// ---------------------------------------------------------------------------
// Device scratch (no cudaMalloc allowed)
// ---------------------------------------------------------------------------
__device__ float          g_pre[Bn * Tn * Dn];          // fp32 pre-activations
__device__ __nv_bfloat16  g_hH[Bn * Tn * Dn];           // hidden hi
__device__ __nv_bfloat16  g_hL[Bn * Tn * Dn];           // hidden lo
__device__ __nv_bfloat16  g_embH[Vn * Dn], g_embL[Vn * Dn];
__device__ __nv_bfloat16  g_w0H[Dn * Dn],  g_w0L[Dn * Dn];
__device__ __nv_bfloat16  g_w1H[Dn * Dn],  g_w1L[Dn * Dn];
__device__ __nv_bfloat16  g_whH[Sn * Dn],  g_whL[Sn * Dn];

// ---------------------------------------------------------------------------
// mma.sync / ldmatrix / cp.async helpers (sm_80-era PTX: legal under compute_103)
// ---------------------------------------------------------------------------
__device__ __forceinline__ uint32_t smem_u32(const void* p) {
    uint32_t a;
    asm("{ .reg .u64 t; cvta.to.shared.u64 t, %1; cvt.u32.u64 %0, t; }"
        : "=r"(a) : "l"(p));
    return a;
}
__device__ __forceinline__ void ldsm4(uint32_t r[4], uint32_t addr) {
    asm volatile("ldmatrix.sync.aligned.m8n8.x4.shared.b16 {%0,%1,%2,%3}, [%4];"
                 : "=r"(r[0]), "=r"(r[1]), "=r"(r[2]), "=r"(r[3]) : "r"(addr));
}
__device__ __forceinline__ void mma_bf16(float d[4], const uint32_t a[4],
                                         const uint32_t b[2]) {
    asm volatile(
        "mma.sync.aligned.m16n8k16.row.col.f32.bf16.bf16.f32 "
        "{%0,%1,%2,%3}, {%4,%5,%6,%7}, {%8,%9}, {%0,%1,%2,%3};"
        : "+f"(d[0]), "+f"(d[1]), "+f"(d[2]), "+f"(d[3])
        : "r"(a[0]), "r"(a[1]), "r"(a[2]), "r"(a[3]), "r"(b[0]), "r"(b[1]));
}
__device__ __forceinline__ void cpa16(uint32_t saddr, const void* g) {
    asm volatile("cp.async.cg.shared.global [%0], [%1], 16;"
                 :: "r"(saddr), "l"(g) : "memory");
}
#define CPA_COMMIT() asm volatile("cp.async.commit_group;" ::: "memory")
#define CPA_WAIT2()  asm volatile("cp.async.wait_group 2;" ::: "memory")

// Fast accurate-enough tanh: MUFU.EX2 + fast divide (abs err ~1e-7).
__device__ __forceinline__ float fast_tanh(float z) {
    float t = __expf(-2.f * fabsf(z));
    float r = __fdividef(t, 1.f + t);
    return copysignf(fmaf(-2.f, r, 1.f), z);
}

// ---------------------------------------------------------------------------
// Tensor-core GEMM (round-8, passing):
// C[M][N] = (AH+AL)[M][256] * (BH+BL)[N][256]^T (+b1[n]+b2[n])
// ---------------------------------------------------------------------------
#define A_PITCH 528
#define B_PITCH 80
#define SM_AH   0
#define SM_AL   (128 * A_PITCH)
#define SM_B    (2 * 128 * A_PITCH)            // 135168
#define B_SEG   (128 * B_PITCH)                // 10240
#define NSTAGE  4
#define GEMM_SMEM (SM_B + NSTAGE * 2 * B_SEG)  // 217088 B

__global__ __launch_bounds__(256, 1) void gemm_mma(
    const __nv_bfloat16* __restrict__ AH, const __nv_bfloat16* __restrict__ AL,
    const int* __restrict__ ids,
    const __nv_bfloat16* __restrict__ BH, const __nv_bfloat16* __restrict__ BL,
    const float* __restrict__ b1, const float* __restrict__ b2,
    float* __restrict__ C, int N)
{
    extern __shared__ char gsm[];
    const uint32_t sb = smem_u32(gsm);

    const int tid = threadIdx.x;
    const int wid = tid >> 5, lane = tid & 31;
    const int warp_m = wid >> 2;
    const int warp_n = wid & 3;
    const int m0 = blockIdx.x * 128;

#pragma unroll 4
    for (int i = tid; i < 4096; i += 256) {
        int row = i >> 5, seg = i & 31;
        int src = ids ? __ldg(ids + m0 + row) : (m0 + row);
        cpa16(sb + SM_AH + row * A_PITCH + seg * 16,
              AH + (size_t)src * 256 + seg * 8);
        cpa16(sb + SM_AL + row * A_PITCH + seg * 16,
              AL + (size_t)src * 256 + seg * 8);
    }
    CPA_COMMIT();

    const int aRow = warp_m * 64 + (lane & 15);
    const uint32_t aOff = (uint32_t)aRow * A_PITCH + ((lane >> 4) * 8) * 2;
    const uint32_t aBaseH = sb + SM_AH + aOff;
    const uint32_t aBaseL = sb + SM_AL + aOff;
    const int bN = warp_n * 32 + (lane & 7) + ((lane >> 4) << 3);
    const uint32_t bOff = (uint32_t)bN * B_PITCH + ((lane >> 3) & 1) * 16;

    const int lrow = tid >> 1;
    const int lseg = (tid & 1) * 2;
    const uint32_t bstW = sb + SM_B + lrow * B_PITCH + lseg * 16;

    const int nTiles = N >> 7;
#pragma unroll 1
    for (int nt = 0; nt < nTiles; nt++) {
        const int n0 = nt << 7;

        float acc[4][4][4];
#pragma unroll
        for (int i = 0; i < 4; i++)
#pragma unroll
            for (int j = 0; j < 4; j++)
#pragma unroll
                for (int r = 0; r < 4; r++) acc[i][j][r] = 0.f;

#pragma unroll
        for (int pc = 0; pc < 3; pc++) {
            const __nv_bfloat16* gh =
                BH + (size_t)(n0 + lrow) * 256 + pc * 32 + lseg * 8;
            const __nv_bfloat16* gl =
                BL + (size_t)(n0 + lrow) * 256 + pc * 32 + lseg * 8;
            uint32_t d = bstW + pc * (2 * B_SEG);
            cpa16(d, gh);             cpa16(d + 16, gh + 8);
            cpa16(d + B_SEG, gl);     cpa16(d + B_SEG + 16, gl + 8);
            CPA_COMMIT();
        }

#pragma unroll 1
        for (int kc = 0; kc < 8; kc++) {
            CPA_WAIT2();
            __syncthreads();

            const uint32_t hiB = sb + SM_B + (uint32_t)(kc & 3) * (2 * B_SEG) + bOff;
            const uint32_t loB = hiB + B_SEG;

            if (kc < 5) {
                const __nv_bfloat16* gh =
                    BH + (size_t)(n0 + lrow) * 256 + (kc + 3) * 32 + lseg * 8;
                const __nv_bfloat16* gl =
                    BL + (size_t)(n0 + lrow) * 256 + (kc + 3) * 32 + lseg * 8;
                uint32_t d = bstW + (uint32_t)((kc + 3) & 3) * (2 * B_SEG);
                cpa16(d, gh);             cpa16(d + 16, gh + 8);
                cpa16(d + B_SEG, gl);     cpa16(d + B_SEG + 16, gl + 8);
            }
            CPA_COMMIT();

#pragma unroll
            for (int kk = 0; kk < 2; kk++) {
                const uint32_t aK = (uint32_t)(kc * 2 + kk) * 32;
                uint32_t aH[4][4], aL[4][4];
#pragma unroll
                for (int i = 0; i < 4; i++) {
                    ldsm4(aH[i], aBaseH + i * (16 * A_PITCH) + aK);
                    ldsm4(aL[i], aBaseL + i * (16 * A_PITCH) + aK);
                }
                uint32_t bH[2][4], bL[2][4];
#pragma unroll
                for (int p = 0; p < 2; p++) {
                    uint32_t o = (uint32_t)p * (16 * B_PITCH) + (uint32_t)kk * 32;
                    ldsm4(bH[p], hiB + o);
                    ldsm4(bL[p], loB + o);
                }
#pragma unroll
                for (int i = 0; i < 4; i++)
#pragma unroll
                    for (int j = 0; j < 4; j++)
                        mma_bf16(acc[i][j], aH[i], &bH[j >> 1][(j & 1) * 2]);
#pragma unroll
                for (int i = 0; i < 4; i++)
#pragma unroll
                    for (int j = 0; j < 4; j++)
                        mma_bf16(acc[i][j], aH[i], &bL[j >> 1][(j & 1) * 2]);
#pragma unroll
                for (int i = 0; i < 4; i++)
#pragma unroll
                    for (int j = 0; j < 4; j++)
                        mma_bf16(acc[i][j], aL[i], &bH[j >> 1][(j & 1) * 2]);
            }
        }

        const int rBase = m0 + warp_m * 64 + (lane >> 2);
        const int cBase = n0 + warp_n * 32 + (lane & 3) * 2;
#pragma unroll
        for (int j = 0; j < 4; j++) {
            const int col = cBase + j * 8;
            float bb0 = 0.f, bb1 = 0.f;
            if (b1) {
                bb0 = b1[col] + b2[col];
                bb1 = b1[col + 1] + b2[col + 1];
            }
#pragma unroll
            for (int i = 0; i < 4; i++) {
                const int row = rBase + i * 16;
                float2 v0 = make_float2(acc[i][j][0] + bb0, acc[i][j][1] + bb1);
                float2 v1 = make_float2(acc[i][j][2] + bb0, acc[i][j][3] + bb1);
                *(float2*)(C + (size_t)row * N + col) = v0;
                *(float2*)(C + (size_t)(row + 8) * N + col) = v1;
            }
        }
    }
}

// ---------------------------------------------------------------------------
// fp32 -> bf16 hi/lo split converter
// ---------------------------------------------------------------------------
__global__ void conv_split(const float* __restrict__ src,
                           __nv_bfloat16* __restrict__ hi,
                           __nv_bfloat16* __restrict__ lo, int n)
{
    int i = blockIdx.x * 256 + threadIdx.x;
    if (i < n) {
        float v = src[i];
        __nv_bfloat16 h = __float2bfloat16(v);
        hi[i] = h;
        lo[i] = __float2bfloat16(v - __bfloat162float(h));
    }
}

// ---------------------------------------------------------------------------
// Recurrence v10: round-4 structure with WREG pushed UP (48->52).
//   h_t = tanh(pre_t + W_hh @ h_{t-1})
// Thread j owns output row j:
//   - W[j][0:208]   in 52 float4 registers (fewer 4-wavefront W LDS/step)
//   - W[:][208:256] in smem, pitch 13 float4 (lanes hit banks
//     0,20,8,28,16,4,24,12 per phase -> conflict-free)
//   - fast_tanh (MUFU) + deferred bf16 emit (post-barrier overlap)
//   - h double-buffered, 1 barrier/step, pre prefetched
// ---------------------------------------------------------------------------
#define WREG 52     // float4's of W per thread in registers (cols 0..207)
#define WSMQ 12     // float4's of W per row in smem        (cols 208..255)
#define WPITCH4 13  // smem W row pitch in float4

__device__ __forceinline__ float rnn_dot(
    const float4* __restrict__ wr, const float4* __restrict__ wsr,
    const float4* __restrict__ hb)
{
    float a0 = 0.f, a1 = 0.f, a2 = 0.f, a3 = 0.f;
#pragma unroll
    for (int q = 0; q < WREG; q++) {
        float4 h = hb[q];
        float4 w = wr[q];
        a0 = fmaf(w.x, h.x, a0);
        a1 = fmaf(w.y, h.y, a1);
        a2 = fmaf(w.z, h.z, a2);
        a3 = fmaf(w.w, h.w, a3);
    }
#pragma unroll
    for (int q = 0; q < WSMQ; q++) {
        float4 h = hb[WREG + q];
        float4 w = wsr[q];
        a0 = fmaf(w.x, h.x, a0);
        a1 = fmaf(w.y, h.y, a1);
        a2 = fmaf(w.z, h.z, a2);
        a3 = fmaf(w.w, h.w, a3);
    }
    return (a0 + a1) + (a2 + a3);
}

extern __shared__ float smem_r[];

__global__ void __launch_bounds__(256, 1) rnn_recur(
    const float* __restrict__ pre,        // [B][T][D]
    const float* __restrict__ Whh,        // [D][D]
    __nv_bfloat16* __restrict__ houtH,    // [B][T][D]
    __nv_bfloat16* __restrict__ houtL)
{
    float4* Wsm = (float4*)smem_r;                 // [256][WPITCH4] float4
    float*  hA  = smem_r + 256 * WPITCH4 * 4;      // 256 floats
    float*  hB  = hA + 256;

    int b = blockIdx.x;
    int j = threadIdx.x;

    // Register W: row j, cols [0, WREG*4)
    float4 wr[WREG];
    {
        const float4* wrow = (const float4*)(Whh + (size_t)j * 256);
#pragma unroll
        for (int q = 0; q < WREG; q++) wr[q] = wrow[q];
    }
    // Smem W: all rows' cols [WREG*4, 256), WSMQ float4 per row
    for (int i = j; i < 256 * WSMQ; i += 256) {
        int r = i / WSMQ, c = i % WSMQ;
        Wsm[r * WPITCH4 + c] =
            ((const float4*)(Whh + (size_t)r * 256 + WREG * 4))[c];
    }

    hA[j] = 0.f;
    __syncthreads();

    const float*   prow = pre   + ((size_t)b * Tn) * Dn;
    __nv_bfloat16* ohr  = houtH + ((size_t)b * Tn) * Dn;
    __nv_bfloat16* olr  = houtL + ((size_t)b * Tn) * Dn;
    const float4*  wsr  = Wsm + j * WPITCH4;

    float pcur = prow[j];

#pragma unroll 1
    for (int step = 0; step < Tn; step += 2) {
        {
            float pnext = prow[Dn + j];
            float s = rnn_dot(wr, wsr, (const float4*)hA);
            float v = fast_tanh(pcur + s);
            hB[j] = v;
            __syncthreads();
            // deferred global emit: overlaps next sub-step's dot issue
            __nv_bfloat16 vh = __float2bfloat16(v);
            ohr[j] = vh;
            olr[j] = __float2bfloat16(v - __bfloat162float(vh));
            pcur = pnext; prow += Dn; ohr += Dn; olr += Dn;
        }
        {
            float pnext = (step + 2 < Tn) ? prow[Dn + j] : 0.f;
            float s = rnn_dot(wr, wsr, (const float4*)hB);
            float v = fast_tanh(pcur + s);
            hA[j] = v;
            __syncthreads();
            __nv_bfloat16 vh = __float2bfloat16(v);
            ohr[j] = vh;
            olr[j] = __float2bfloat16(v - __bfloat162float(vh));
            pcur = pnext; prow += Dn; ohr += Dn; olr += Dn;
        }
    }
}

// ---------------------------------------------------------------------------
extern "C" void kernel_launch(void* const* d_in, const int* in_sizes, int n_in,
                              void* d_out, int out_size)
{
    (void)in_sizes; (void)n_in; (void)out_size;

    const int*   ids   = (const int*)  d_in[0];
    const float* emb   = (const float*)d_in[1];
    const float* Wih0  = (const float*)d_in[2];
    const float* Whh0  = (const float*)d_in[3];
    const float* bih0  = (const float*)d_in[4];
    const float* bhh0  = (const float*)d_in[5];
    const float* Wih1  = (const float*)d_in[6];
    const float* Whh1  = (const float*)d_in[7];
    const float* bih1  = (const float*)d_in[8];
    const float* bhh1  = (const float*)d_in[9];
    const float* Whead = (const float*)d_in[10];
    float* out = (float*)d_out;

    float *pre;           cudaGetSymbolAddress((void**)&pre,  g_pre);
    __nv_bfloat16 *hH;    cudaGetSymbolAddress((void**)&hH,   g_hH);
    __nv_bfloat16 *hL;    cudaGetSymbolAddress((void**)&hL,   g_hL);
    __nv_bfloat16 *embH;  cudaGetSymbolAddress((void**)&embH, g_embH);
    __nv_bfloat16 *embL;  cudaGetSymbolAddress((void**)&embL, g_embL);
    __nv_bfloat16 *w0H;   cudaGetSymbolAddress((void**)&w0H,  g_w0H);
    __nv_bfloat16 *w0L;   cudaGetSymbolAddress((void**)&w0L,  g_w0L);
    __nv_bfloat16 *w1H;   cudaGetSymbolAddress((void**)&w1H,  g_w1H);
    __nv_bfloat16 *w1L;   cudaGetSymbolAddress((void**)&w1L,  g_w1L);
    __nv_bfloat16 *whH;   cudaGetSymbolAddress((void**)&whH,  g_whH);
    __nv_bfloat16 *whL;   cudaGetSymbolAddress((void**)&whL,  g_whL);

    const int recur_smem = (256 * WPITCH4 * 4 + 512) * 4;   // 55296 B
    cudaFuncSetAttribute(rnn_recur, cudaFuncAttributeMaxDynamicSharedMemorySize,
                         recur_smem);
    cudaFuncSetAttribute(gemm_mma, cudaFuncAttributeMaxDynamicSharedMemorySize,
                         GEMM_SMEM);

    // Weight / embedding bf16 hi-lo splits
    conv_split<<<(Vn * Dn + 255) / 256, 256>>>(emb,   embH, embL, Vn * Dn);
    conv_split<<<(Dn * Dn + 255) / 256, 256>>>(Wih0,  w0H,  w0L,  Dn * Dn);
    conv_split<<<(Dn * Dn + 255) / 256, 256>>>(Wih1,  w1H,  w1L,  Dn * Dn);
    conv_split<<<(Sn * Dn + 255) / 256, 256>>>(Whead, whH,  whL,  Sn * Dn);

    const int M = Bn * Tn;   // 65536

    // pre0 = emb[ids] @ W_ih0^T + (b_ih0 + b_hh0)
    gemm_mma<<<M / 128, 256, GEMM_SMEM>>>(embH, embL, ids, w0H, w0L,
                                          bih0, bhh0, pre, Dn);
    // h1 recurrence (emits bf16 hi/lo)
    rnn_recur<<<Bn, 256, recur_smem>>>(pre, Whh0, hH, hL);
    // pre1 = h1 @ W_ih1^T + (b_ih1 + b_hh1)
    gemm_mma<<<M / 128, 256, GEMM_SMEM>>>(hH, hL, nullptr, w1H, w1L,
                                          bih1, bhh1, pre, Dn);
    // h2 recurrence
    rnn_recur<<<Bn, 256, recur_smem>>>(pre, Whh1, hH, hL);
    // logits = h2 @ W_head^T
    gemm_mma<<<M / 128, 256, GEMM_SMEM>>>(hH, hL, nullptr, whH, whL,
                                          nullptr, nullptr, out, Sn);
}

// round 14
// speedup vs baseline: 1.0324x; 1.0324x over previous
#include <cuda_runtime.h>
#include <cuda_bf16.h>
#include <math.h>
#include <stdint.h>

#define Bn 128
#define Tn 512
#define Dn 256
#define Vn 4096
#define Sn 512

// ---------------------------------------------------------------------------
// Device scratch (no cudaMalloc allowed)
// ---------------------------------------------------------------------------
__device__ float          g_pre[Bn * Tn * Dn];          // fp32 pre-activations
__device__ __nv_bfloat16  g_hH[Bn * Tn * Dn];           // hidden hi
__device__ __nv_bfloat16  g_hL[Bn * Tn * Dn];           // hidden lo
__device__ __nv_bfloat16  g_embH[Vn * Dn], g_embL[Vn * Dn];
__device__ __nv_bfloat16  g_w0H[Dn * Dn],  g_w0L[Dn * Dn];
__device__ __nv_bfloat16  g_w1H[Dn * Dn],  g_w1L[Dn * Dn];
__device__ __nv_bfloat16  g_whH[Sn * Dn],  g_whL[Sn * Dn];

// ---------------------------------------------------------------------------
// mma.sync / ldmatrix / cp.async helpers (sm_80-era PTX: legal under compute_103)
// ---------------------------------------------------------------------------
__device__ __forceinline__ uint32_t smem_u32(const void* p) {
    uint32_t a;
    asm("{ .reg .u64 t; cvta.to.shared.u64 t, %1; cvt.u32.u64 %0, t; }"
        : "=r"(a) : "l"(p));
    return a;
}
__device__ __forceinline__ void ldsm4(uint32_t r[4], uint32_t addr) {
    asm volatile("ldmatrix.sync.aligned.m8n8.x4.shared.b16 {%0,%1,%2,%3}, [%4];"
                 : "=r"(r[0]), "=r"(r[1]), "=r"(r[2]), "=r"(r[3]) : "r"(addr));
}
__device__ __forceinline__ void mma_bf16(float d[4], const uint32_t a[4],
                                         const uint32_t b[2]) {
    asm volatile(
        "mma.sync.aligned.m16n8k16.row.col.f32.bf16.bf16.f32 "
        "{%0,%1,%2,%3}, {%4,%5,%6,%7}, {%8,%9}, {%0,%1,%2,%3};"
        : "+f"(d[0]), "+f"(d[1]), "+f"(d[2]), "+f"(d[3])
        : "r"(a[0]), "r"(a[1]), "r"(a[2]), "r"(a[3]), "r"(b[0]), "r"(b[1]));
}
__device__ __forceinline__ void cpa16(uint32_t saddr, const void* g) {
    asm volatile("cp.async.cg.shared.global [%0], [%1], 16;"
                 :: "r"(saddr), "l"(g) : "memory");
}
#define CPA_COMMIT() asm volatile("cp.async.commit_group;" ::: "memory")
#define CPA_WAIT2()  asm volatile("cp.async.wait_group 2;" ::: "memory")

// ---------------------------------------------------------------------------
// Tensor-core GEMM, M_TILE=64 (wave-quantization fix: 1024 CTAs / 148 SMs
// = 98.8% wave efficiency vs 86.5% at M_TILE=128):
// C[M][N] = (AH+AL)[M][256] * (BH+BL)[N][256]^T (+b1[n]+b2[n])
// bf16 hi/lo split (3 products), fp32 register accumulate.
// cp.async 4-stage pipeline for B; A tile resident; 8 warps = 2(m)x4(n),
// each warp 32x32 per n-tile.
// ---------------------------------------------------------------------------
#define MT      64
#define A_PITCH 528
#define B_PITCH 80
#define SM_AH   0
#define SM_AL   (MT * A_PITCH)                 // 33792
#define SM_B    (2 * MT * A_PITCH)             // 67584
#define B_SEG   (128 * B_PITCH)                // 10240
#define NSTAGE  4
#define GEMM_SMEM (SM_B + NSTAGE * 2 * B_SEG)  // 149504 B

__global__ __launch_bounds__(256, 1) void gemm_mma(
    const __nv_bfloat16* __restrict__ AH, const __nv_bfloat16* __restrict__ AL,
    const int* __restrict__ ids,
    const __nv_bfloat16* __restrict__ BH, const __nv_bfloat16* __restrict__ BL,
    const float* __restrict__ b1, const float* __restrict__ b2,
    float* __restrict__ C, int N)
{
    extern __shared__ char gsm[];
    const uint32_t sb = smem_u32(gsm);

    const int tid = threadIdx.x;
    const int wid = tid >> 5, lane = tid & 31;
    const int warp_m = wid >> 2;       // 0..1, 32 rows each
    const int warp_n = wid & 3;        // 0..3, 32 cols each
    const int m0 = blockIdx.x * MT;

    // ---- A tile (64 x 256, hi+lo) via cp.async; one commit group ----
#pragma unroll 4
    for (int i = tid; i < 2048; i += 256) {
        int row = i >> 5, seg = i & 31;
        int src = ids ? __ldg(ids + m0 + row) : (m0 + row);
        cpa16(sb + SM_AH + row * A_PITCH + seg * 16,
              AH + (size_t)src * 256 + seg * 8);
        cpa16(sb + SM_AL + row * A_PITCH + seg * 16,
              AL + (size_t)src * 256 + seg * 8);
    }
    CPA_COMMIT();

    // ---- Per-lane ldmatrix addresses ----
    const int aRow = warp_m * 32 + (lane & 15);
    const uint32_t aOff = (uint32_t)aRow * A_PITCH + ((lane >> 4) * 8) * 2;
    const uint32_t aBaseH = sb + SM_AH + aOff;
    const uint32_t aBaseL = sb + SM_AL + aOff;
    const int bN = warp_n * 32 + (lane & 7) + ((lane >> 4) << 3);
    const uint32_t bOff = (uint32_t)bN * B_PITCH + ((lane >> 3) & 1) * 16;

    // ---- B chunk loader mapping (per thread: 2 x 16B per half) ----
    const int lrow = tid >> 1;
    const int lseg = (tid & 1) * 2;
    const uint32_t bstW = sb + SM_B + lrow * B_PITCH + lseg * 16;

    const int nTiles = N >> 7;
#pragma unroll 1
    for (int nt = 0; nt < nTiles; nt++) {
        const int n0 = nt << 7;

        float acc[2][4][4];
#pragma unroll
        for (int i = 0; i < 2; i++)
#pragma unroll
            for (int j = 0; j < 4; j++)
#pragma unroll
                for (int r = 0; r < 4; r++) acc[i][j][r] = 0.f;

        // prologue: issue stages 0..2
#pragma unroll
        for (int pc = 0; pc < 3; pc++) {
            const __nv_bfloat16* gh =
                BH + (size_t)(n0 + lrow) * 256 + pc * 32 + lseg * 8;
            const __nv_bfloat16* gl =
                BL + (size_t)(n0 + lrow) * 256 + pc * 32 + lseg * 8;
            uint32_t d = bstW + pc * (2 * B_SEG);
            cpa16(d, gh);             cpa16(d + 16, gh + 8);
            cpa16(d + B_SEG, gl);     cpa16(d + B_SEG + 16, gl + 8);
            CPA_COMMIT();
        }

#pragma unroll 1
        for (int kc = 0; kc < 8; kc++) {
            CPA_WAIT2();
            __syncthreads();

            const uint32_t hiB = sb + SM_B + (uint32_t)(kc & 3) * (2 * B_SEG) + bOff;
            const uint32_t loB = hiB + B_SEG;

            if (kc < 5) {
                const __nv_bfloat16* gh =
                    BH + (size_t)(n0 + lrow) * 256 + (kc + 3) * 32 + lseg * 8;
                const __nv_bfloat16* gl =
                    BL + (size_t)(n0 + lrow) * 256 + (kc + 3) * 32 + lseg * 8;
                uint32_t d = bstW + (uint32_t)((kc + 3) & 3) * (2 * B_SEG);
                cpa16(d, gh);             cpa16(d + 16, gh + 8);
                cpa16(d + B_SEG, gl);     cpa16(d + B_SEG + 16, gl + 8);
            }
            CPA_COMMIT();

#pragma unroll
            for (int kk = 0; kk < 2; kk++) {
                const uint32_t aK = (uint32_t)(kc * 2 + kk) * 32;
                uint32_t aH[2][4], aL[2][4];
#pragma unroll
                for (int i = 0; i < 2; i++) {
                    ldsm4(aH[i], aBaseH + i * (16 * A_PITCH) + aK);
                    ldsm4(aL[i], aBaseL + i * (16 * A_PITCH) + aK);
                }
                uint32_t bH[2][4], bL[2][4];
#pragma unroll
                for (int p = 0; p < 2; p++) {
                    uint32_t o = (uint32_t)p * (16 * B_PITCH) + (uint32_t)kk * 32;
                    ldsm4(bH[p], hiB + o);
                    ldsm4(bL[p], loB + o);
                }
#pragma unroll
                for (int i = 0; i < 2; i++)
#pragma unroll
                    for (int j = 0; j < 4; j++)
                        mma_bf16(acc[i][j], aH[i], &bH[j >> 1][(j & 1) * 2]);
#pragma unroll
                for (int i = 0; i < 2; i++)
#pragma unroll
                    for (int j = 0; j < 4; j++)
                        mma_bf16(acc[i][j], aH[i], &bL[j >> 1][(j & 1) * 2]);
#pragma unroll
                for (int i = 0; i < 2; i++)
#pragma unroll
                    for (int j = 0; j < 4; j++)
                        mma_bf16(acc[i][j], aL[i], &bH[j >> 1][(j & 1) * 2]);
            }
        }

        // ---- Epilogue: add bias, store fp32 C ----
        const int rBase = m0 + warp_m * 32 + (lane >> 2);
        const int cBase = n0 + warp_n * 32 + (lane & 3) * 2;
#pragma unroll
        for (int j = 0; j < 4; j++) {
            const int col = cBase + j * 8;
            float bb0 = 0.f, bb1 = 0.f;
            if (b1) {
                bb0 = b1[col] + b2[col];
                bb1 = b1[col + 1] + b2[col + 1];
            }
#pragma unroll
            for (int i = 0; i < 2; i++) {
                const int row = rBase + i * 16;
                float2 v0 = make_float2(acc[i][j][0] + bb0, acc[i][j][1] + bb1);
                float2 v1 = make_float2(acc[i][j][2] + bb0, acc[i][j][3] + bb1);
                *(float2*)(C + (size_t)row * N + col) = v0;
                *(float2*)(C + (size_t)(row + 8) * N + col) = v1;
            }
        }
    }
}

// ---------------------------------------------------------------------------
// fp32 -> bf16 hi/lo split: ALL four tables in one launch
// segments: emb [0, 1048576), w0 [.., +65536), w1 [.., +65536), wh [.., +131072)
// ---------------------------------------------------------------------------
#define SEG0 (Vn * Dn)              // 1048576
#define SEG1 (SEG0 + Dn * Dn)       // 1114112
#define SEG2 (SEG1 + Dn * Dn)       // 1179648
#define SEG3 (SEG2 + Sn * Dn)       // 1310720

__global__ void conv_all(
    const float* __restrict__ emb, const float* __restrict__ w0,
    const float* __restrict__ w1,  const float* __restrict__ wh,
    __nv_bfloat16* __restrict__ embH, __nv_bfloat16* __restrict__ embL,
    __nv_bfloat16* __restrict__ w0H,  __nv_bfloat16* __restrict__ w0L,
    __nv_bfloat16* __restrict__ w1H,  __nv_bfloat16* __restrict__ w1L,
    __nv_bfloat16* __restrict__ whH,  __nv_bfloat16* __restrict__ whL)
{
    int i = blockIdx.x * 256 + threadIdx.x;
    if (i >= SEG3) return;
    const float* src;
    __nv_bfloat16 *hi, *lo;
    int k;
    if (i < SEG0)      { src = emb; hi = embH; lo = embL; k = i; }
    else if (i < SEG1) { src = w0;  hi = w0H;  lo = w0L;  k = i - SEG0; }
    else if (i < SEG2) { src = w1;  hi = w1H;  lo = w1L;  k = i - SEG1; }
    else               { src = wh;  hi = whH;  lo = whL;  k = i - SEG2; }
    float v = src[k];
    __nv_bfloat16 h = __float2bfloat16(v);
    hi[k] = h;
    lo[k] = __float2bfloat16(v - __bfloat162float(h));
}

// ---------------------------------------------------------------------------
// Recurrence (round-4 champion, byte-identical — empirically optimal after
// 7 alternative designs all regressed): one CTA per batch row, 512 steps.
//   h_t = tanh(pre_t + W_hh @ h_{t-1})
// Thread j owns output row j: W[j][0:192] in 48 float4 registers,
// W[:][192:256] via smem pitch-17-float4; h double-buffered, 1 barrier/step.
// Emits h as bf16 hi/lo for the GEMM A-operand.
// ---------------------------------------------------------------------------
#define WREG 48
#define WSMQ 16
#define WPITCH4 17

__device__ __forceinline__ float rnn_dot(
    const float4* __restrict__ wr, const float4* __restrict__ wsr,
    const float4* __restrict__ hb)
{
    float a0 = 0.f, a1 = 0.f, a2 = 0.f, a3 = 0.f;
#pragma unroll
    for (int q = 0; q < WREG; q++) {
        float4 h = hb[q];
        float4 w = wr[q];
        a0 = fmaf(w.x, h.x, a0);
        a1 = fmaf(w.y, h.y, a1);
        a2 = fmaf(w.z, h.z, a2);
        a3 = fmaf(w.w, h.w, a3);
    }
#pragma unroll
    for (int q = 0; q < WSMQ; q++) {
        float4 h = hb[WREG + q];
        float4 w = wsr[q];
        a0 = fmaf(w.x, h.x, a0);
        a1 = fmaf(w.y, h.y, a1);
        a2 = fmaf(w.z, h.z, a2);
        a3 = fmaf(w.w, h.w, a3);
    }
    return (a0 + a1) + (a2 + a3);
}

extern __shared__ float smem_r[];

__global__ void __launch_bounds__(256, 1) rnn_recur(
    const float* __restrict__ pre,        // [B][T][D]
    const float* __restrict__ Whh,        // [D][D]
    __nv_bfloat16* __restrict__ houtH,    // [B][T][D]
    __nv_bfloat16* __restrict__ houtL)
{
    float4* Wsm = (float4*)smem_r;
    float*  hA  = smem_r + 256 * WPITCH4 * 4;
    float*  hB  = hA + 256;

    int b = blockIdx.x;
    int j = threadIdx.x;

    float4 wr[WREG];
    {
        const float4* wrow = (const float4*)(Whh + (size_t)j * 256);
#pragma unroll
        for (int q = 0; q < WREG; q++) wr[q] = wrow[q];
    }
    for (int i = j; i < 256 * WSMQ; i += 256) {
        int r = i >> 4, c = i & 15;
        Wsm[r * WPITCH4 + c] =
            ((const float4*)(Whh + (size_t)r * 256 + WREG * 4))[c];
    }

    hA[j] = 0.f;
    __syncthreads();

    const float*   prow = pre   + ((size_t)b * Tn) * Dn;
    __nv_bfloat16* ohr  = houtH + ((size_t)b * Tn) * Dn;
    __nv_bfloat16* olr  = houtL + ((size_t)b * Tn) * Dn;
    const float4*  wsr  = Wsm + j * WPITCH4;

    float pcur = prow[j];

#pragma unroll 1
    for (int step = 0; step < Tn; step += 2) {
        {
            float pnext = prow[Dn + j];
            float s = rnn_dot(wr, wsr, (const float4*)hA);
            float v = tanhf(pcur + s);
            hB[j] = v;
            __nv_bfloat16 vh = __float2bfloat16(v);
            ohr[j] = vh;
            olr[j] = __float2bfloat16(v - __bfloat162float(vh));
            __syncthreads();
            pcur = pnext; prow += Dn; ohr += Dn; olr += Dn;
        }
        {
            float pnext = (step + 2 < Tn) ? prow[Dn + j] : 0.f;
            float s = rnn_dot(wr, wsr, (const float4*)hB);
            float v = tanhf(pcur + s);
            hA[j] = v;
            __nv_bfloat16 vh = __float2bfloat16(v);
            ohr[j] = vh;
            olr[j] = __float2bfloat16(v - __bfloat162float(vh));
            __syncthreads();
            pcur = pnext; prow += Dn; ohr += Dn; olr += Dn;
        }
    }
}

// ---------------------------------------------------------------------------
extern "C" void kernel_launch(void* const* d_in, const int* in_sizes, int n_in,
                              void* d_out, int out_size)
{
    (void)in_sizes; (void)n_in; (void)out_size;

    const int*   ids   = (const int*)  d_in[0];
    const float* emb   = (const float*)d_in[1];
    const float* Wih0  = (const float*)d_in[2];
    const float* Whh0  = (const float*)d_in[3];
    const float* bih0  = (const float*)d_in[4];
    const float* bhh0  = (const float*)d_in[5];
    const float* Wih1  = (const float*)d_in[6];
    const float* Whh1  = (const float*)d_in[7];
    const float* bih1  = (const float*)d_in[8];
    const float* bhh1  = (const float*)d_in[9];
    const float* Whead = (const float*)d_in[10];
    float* out = (float*)d_out;

    float *pre;           cudaGetSymbolAddress((void**)&pre,  g_pre);
    __nv_bfloat16 *hH;    cudaGetSymbolAddress((void**)&hH,   g_hH);
    __nv_bfloat16 *hL;    cudaGetSymbolAddress((void**)&hL,   g_hL);
    __nv_bfloat16 *embH;  cudaGetSymbolAddress((void**)&embH, g_embH);
    __nv_bfloat16 *embL;  cudaGetSymbolAddress((void**)&embL, g_embL);
    __nv_bfloat16 *w0H;   cudaGetSymbolAddress((void**)&w0H,  g_w0H);
    __nv_bfloat16 *w0L;   cudaGetSymbolAddress((void**)&w0L,  g_w0L);
    __nv_bfloat16 *w1H;   cudaGetSymbolAddress((void**)&w1H,  g_w1H);
    __nv_bfloat16 *w1L;   cudaGetSymbolAddress((void**)&w1L,  g_w1L);
    __nv_bfloat16 *whH;   cudaGetSymbolAddress((void**)&whH,  g_whH);
    __nv_bfloat16 *whL;   cudaGetSymbolAddress((void**)&whL,  g_whL);

    const int recur_smem = (256 * WPITCH4 * 4 + 512) * 4;   // 71680 B
    cudaFuncSetAttribute(rnn_recur, cudaFuncAttributeMaxDynamicSharedMemorySize,
                         recur_smem);
    cudaFuncSetAttribute(gemm_mma, cudaFuncAttributeMaxDynamicSharedMemorySize,
                         GEMM_SMEM);

    // All four bf16 hi/lo splits in one launch
    conv_all<<<(SEG3 + 255) / 256, 256>>>(emb, Wih0, Wih1, Whead,
                                          embH, embL, w0H, w0L,
                                          w1H, w1L, whH, whL);

    const int M = Bn * Tn;   // 65536

    // pre0 = emb[ids] @ W_ih0^T + (b_ih0 + b_hh0)
    gemm_mma<<<M / MT, 256, GEMM_SMEM>>>(embH, embL, ids, w0H, w0L,
                                         bih0, bhh0, pre, Dn);
    // h1 recurrence (emits bf16 hi/lo)
    rnn_recur<<<Bn, 256, recur_smem>>>(pre, Whh0, hH, hL);
    // pre1 = h1 @ W_ih1^T + (b_ih1 + b_hh1)
    gemm_mma<<<M / MT, 256, GEMM_SMEM>>>(hH, hL, nullptr, w1H, w1L,
                                         bih1, bhh1, pre, Dn);
    // h2 recurrence
    rnn_recur<<<Bn, 256, recur_smem>>>(pre, Whh1, hH, hL);
    // logits = h2 @ W_head^T
    gemm_mma<<<M / MT, 256, GEMM_SMEM>>>(hH, hL, nullptr, whH, whL,
                                         nullptr, nullptr, out, Sn);
}

// round 15
// speedup vs baseline: 1.0637x; 1.0303x over previous
#include <cuda_runtime.h>
#include <cuda_bf16.h>
#include <math.h>
#include <stdint.h>

#define Bn 128
#define Tn 512
#define Dn 256
#define Vn 4096
#define Sn 512

// ---------------------------------------------------------------------------
// Device scratch (no cudaMalloc allowed)
// ---------------------------------------------------------------------------
__device__ float          g_pre[Bn * Tn * Dn];          // fp32 pre-activations
__device__ __nv_bfloat16  g_hH[Bn * Tn * Dn];           // hidden hi
__device__ __nv_bfloat16  g_hL[Bn * Tn * Dn];           // hidden lo
__device__ __nv_bfloat16  g_embH[Vn * Dn], g_embL[Vn * Dn];
__device__ __nv_bfloat16  g_w0H[Dn * Dn],  g_w0L[Dn * Dn];
__device__ __nv_bfloat16  g_w1H[Dn * Dn],  g_w1L[Dn * Dn];
__device__ __nv_bfloat16  g_whH[Sn * Dn],  g_whL[Sn * Dn];

// ---------------------------------------------------------------------------
// mma.sync / ldmatrix / cp.async helpers (sm_80-era PTX: legal under compute_103)
// ---------------------------------------------------------------------------
__device__ __forceinline__ uint32_t smem_u32(const void* p) {
    uint32_t a;
    asm("{ .reg .u64 t; cvta.to.shared.u64 t, %1; cvt.u32.u64 %0, t; }"
        : "=r"(a) : "l"(p));
    return a;
}
__device__ __forceinline__ void ldsm4(uint32_t r[4], uint32_t addr) {
    asm volatile("ldmatrix.sync.aligned.m8n8.x4.shared.b16 {%0,%1,%2,%3}, [%4];"
                 : "=r"(r[0]), "=r"(r[1]), "=r"(r[2]), "=r"(r[3]) : "r"(addr));
}
__device__ __forceinline__ void mma_bf16(float d[4], const uint32_t a[4],
                                         const uint32_t b[2]) {
    asm volatile(
        "mma.sync.aligned.m16n8k16.row.col.f32.bf16.bf16.f32 "
        "{%0,%1,%2,%3}, {%4,%5,%6,%7}, {%8,%9}, {%0,%1,%2,%3};"
        : "+f"(d[0]), "+f"(d[1]), "+f"(d[2]), "+f"(d[3])
        : "r"(a[0]), "r"(a[1]), "r"(a[2]), "r"(a[3]), "r"(b[0]), "r"(b[1]));
}
__device__ __forceinline__ void cpa16(uint32_t saddr, const void* g) {
    asm volatile("cp.async.cg.shared.global [%0], [%1], 16;"
                 :: "r"(saddr), "l"(g) : "memory");
}
#define CPA_COMMIT() asm volatile("cp.async.commit_group;" ::: "memory")
#define CPA_WAIT1()  asm volatile("cp.async.wait_group 1;" ::: "memory")

// ---------------------------------------------------------------------------
// Tensor-core GEMM, MT=64, 2-stage B pipeline, smem 108544 B -> 2 CTAs/SM
// (fix for measured occ=12.4%/tensor=38.4%: 16 warps/SM hide LDSM+MMA latency)
// C[M][N] = (AH+AL)[M][256] * (BH+BL)[N][256]^T (+b1[n]+b2[n])
// bf16 hi/lo split (3 products), fp32 register accumulate.
// ---------------------------------------------------------------------------
#define MT      64
#define A_PITCH 528
#define B_PITCH 80
#define SM_AH   0
#define SM_AL   (MT * A_PITCH)                 // 33792
#define SM_B    (2 * MT * A_PITCH)             // 67584
#define B_SEG   (128 * B_PITCH)                // 10240
#define GEMM_SMEM (SM_B + 2 * 2 * B_SEG)       // 108544 B -> 2 CTAs/SM

__global__ __launch_bounds__(256) void gemm_mma(
    const __nv_bfloat16* __restrict__ AH, const __nv_bfloat16* __restrict__ AL,
    const int* __restrict__ ids,
    const __nv_bfloat16* __restrict__ BH, const __nv_bfloat16* __restrict__ BL,
    const float* __restrict__ b1, const float* __restrict__ b2,
    float* __restrict__ C, int N)
{
    extern __shared__ char gsm[];
    const uint32_t sb = smem_u32(gsm);

    const int tid = threadIdx.x;
    const int wid = tid >> 5, lane = tid & 31;
    const int warp_m = wid >> 2;       // 0..1, 32 rows each
    const int warp_n = wid & 3;        // 0..3, 32 cols each
    const int m0 = blockIdx.x * MT;

    // ---- A tile (64 x 256, hi+lo) via cp.async; one commit group ----
#pragma unroll 4
    for (int i = tid; i < 2048; i += 256) {
        int row = i >> 5, seg = i & 31;
        int src = ids ? __ldg(ids + m0 + row) : (m0 + row);
        cpa16(sb + SM_AH + row * A_PITCH + seg * 16,
              AH + (size_t)src * 256 + seg * 8);
        cpa16(sb + SM_AL + row * A_PITCH + seg * 16,
              AL + (size_t)src * 256 + seg * 8);
    }
    CPA_COMMIT();

    // ---- Per-lane ldmatrix addresses ----
    const int aRow = warp_m * 32 + (lane & 15);
    const uint32_t aOff = (uint32_t)aRow * A_PITCH + ((lane >> 4) * 8) * 2;
    const uint32_t aBaseH = sb + SM_AH + aOff;
    const uint32_t aBaseL = sb + SM_AL + aOff;
    const int bN = warp_n * 32 + (lane & 7) + ((lane >> 4) << 3);
    const uint32_t bOff = (uint32_t)bN * B_PITCH + ((lane >> 3) & 1) * 16;

    // ---- B chunk loader mapping (per thread: 2 x 16B per half) ----
    const int lrow = tid >> 1;
    const int lseg = (tid & 1) * 2;
    const uint32_t bstW = sb + SM_B + lrow * B_PITCH + lseg * 16;

    const int nTiles = N >> 7;
#pragma unroll 1
    for (int nt = 0; nt < nTiles; nt++) {
        const int n0 = nt << 7;

        float acc[2][4][4];
#pragma unroll
        for (int i = 0; i < 2; i++)
#pragma unroll
            for (int j = 0; j < 4; j++)
#pragma unroll
                for (int r = 0; r < 4; r++) acc[i][j][r] = 0.f;

        // prologue: issue stages 0 and 1 (one commit group each)
#pragma unroll
        for (int pc = 0; pc < 2; pc++) {
            const __nv_bfloat16* gh =
                BH + (size_t)(n0 + lrow) * 256 + pc * 32 + lseg * 8;
            const __nv_bfloat16* gl =
                BL + (size_t)(n0 + lrow) * 256 + pc * 32 + lseg * 8;
            uint32_t d = bstW + pc * (2 * B_SEG);
            cpa16(d, gh);             cpa16(d + 16, gh + 8);
            cpa16(d + B_SEG, gl);     cpa16(d + B_SEG + 16, gl + 8);
            CPA_COMMIT();
        }

#pragma unroll 1
        for (int kc = 0; kc < 8; kc++) {
            CPA_WAIT1();            // stage kc (and A, nt=0) complete
            __syncthreads();

            const uint32_t hiB = sb + SM_B + (uint32_t)(kc & 1) * (2 * B_SEG) + bOff;
            const uint32_t loB = hiB + B_SEG;

            // MMA over this chunk (two k16 steps)
#pragma unroll
            for (int kk = 0; kk < 2; kk++) {
                const uint32_t aK = (uint32_t)(kc * 2 + kk) * 32;
                uint32_t aH[2][4], aL[2][4];
#pragma unroll
                for (int i = 0; i < 2; i++) {
                    ldsm4(aH[i], aBaseH + i * (16 * A_PITCH) + aK);
                    ldsm4(aL[i], aBaseL + i * (16 * A_PITCH) + aK);
                }
                uint32_t bH[2][4], bL[2][4];
#pragma unroll
                for (int p = 0; p < 2; p++) {
                    uint32_t o = (uint32_t)p * (16 * B_PITCH) + (uint32_t)kk * 32;
                    ldsm4(bH[p], hiB + o);
                    ldsm4(bL[p], loB + o);
                }
#pragma unroll
                for (int i = 0; i < 2; i++)
#pragma unroll
                    for (int j = 0; j < 4; j++)
                        mma_bf16(acc[i][j], aH[i], &bH[j >> 1][(j & 1) * 2]);
#pragma unroll
                for (int i = 0; i < 2; i++)
#pragma unroll
                    for (int j = 0; j < 4; j++)
                        mma_bf16(acc[i][j], aH[i], &bL[j >> 1][(j & 1) * 2]);
#pragma unroll
                for (int i = 0; i < 2; i++)
#pragma unroll
                    for (int j = 0; j < 4; j++)
                        mma_bf16(acc[i][j], aL[i], &bH[j >> 1][(j & 1) * 2]);
            }

            __syncthreads();        // stage kc reads complete CTA-wide

            // refill slot kc&1 with stage kc+2 (empty commit when drained,
            // keeping the group count uniform for CPA_WAIT1)
            if (kc < 6) {
                const __nv_bfloat16* gh =
                    BH + (size_t)(n0 + lrow) * 256 + (kc + 2) * 32 + lseg * 8;
                const __nv_bfloat16* gl =
                    BL + (size_t)(n0 + lrow) * 256 + (kc + 2) * 32 + lseg * 8;
                uint32_t d = bstW + (uint32_t)(kc & 1) * (2 * B_SEG);
                cpa16(d, gh);             cpa16(d + 16, gh + 8);
                cpa16(d + B_SEG, gl);     cpa16(d + B_SEG + 16, gl + 8);
            }
            CPA_COMMIT();
        }

        // ---- Epilogue: add bias, store fp32 C ----
        const int rBase = m0 + warp_m * 32 + (lane >> 2);
        const int cBase = n0 + warp_n * 32 + (lane & 3) * 2;
#pragma unroll
        for (int j = 0; j < 4; j++) {
            const int col = cBase + j * 8;
            float bb0 = 0.f, bb1 = 0.f;
            if (b1) {
                bb0 = b1[col] + b2[col];
                bb1 = b1[col + 1] + b2[col + 1];
            }
#pragma unroll
            for (int i = 0; i < 2; i++) {
                const int row = rBase + i * 16;
                float2 v0 = make_float2(acc[i][j][0] + bb0, acc[i][j][1] + bb1);
                float2 v1 = make_float2(acc[i][j][2] + bb0, acc[i][j][3] + bb1);
                *(float2*)(C + (size_t)row * N + col) = v0;
                *(float2*)(C + (size_t)(row + 8) * N + col) = v1;
            }
        }
    }
}

// ---------------------------------------------------------------------------
// fp32 -> bf16 hi/lo split: ALL four tables in one launch
// ---------------------------------------------------------------------------
#define SEG0 (Vn * Dn)              // 1048576
#define SEG1 (SEG0 + Dn * Dn)       // 1114112
#define SEG2 (SEG1 + Dn * Dn)       // 1179648
#define SEG3 (SEG2 + Sn * Dn)       // 1310720

__global__ void conv_all(
    const float* __restrict__ emb, const float* __restrict__ w0,
    const float* __restrict__ w1,  const float* __restrict__ wh,
    __nv_bfloat16* __restrict__ embH, __nv_bfloat16* __restrict__ embL,
    __nv_bfloat16* __restrict__ w0H,  __nv_bfloat16* __restrict__ w0L,
    __nv_bfloat16* __restrict__ w1H,  __nv_bfloat16* __restrict__ w1L,
    __nv_bfloat16* __restrict__ whH,  __nv_bfloat16* __restrict__ whL)
{
    int i = blockIdx.x * 256 + threadIdx.x;
    if (i >= SEG3) return;
    const float* src;
    __nv_bfloat16 *hi, *lo;
    int k;
    if (i < SEG0)      { src = emb; hi = embH; lo = embL; k = i; }
    else if (i < SEG1) { src = w0;  hi = w0H;  lo = w0L;  k = i - SEG0; }
    else if (i < SEG2) { src = w1;  hi = w1H;  lo = w1L;  k = i - SEG1; }
    else               { src = wh;  hi = whH;  lo = whL;  k = i - SEG2; }
    float v = src[k];
    __nv_bfloat16 h = __float2bfloat16(v);
    hi[k] = h;
    lo[k] = __float2bfloat16(v - __bfloat162float(h));
}

// ---------------------------------------------------------------------------
// Recurrence (round-4 champion, byte-identical — empirically optimal after
// 7 alternative designs all regressed): one CTA per batch row, 512 steps.
//   h_t = tanh(pre_t + W_hh @ h_{t-1})
// Thread j owns output row j: W[j][0:192] in 48 float4 registers,
// W[:][192:256] via smem pitch-17-float4; h double-buffered, 1 barrier/step.
// Emits h as bf16 hi/lo for the GEMM A-operand.
// ---------------------------------------------------------------------------
#define WREG 48
#define WSMQ 16
#define WPITCH4 17

__device__ __forceinline__ float rnn_dot(
    const float4* __restrict__ wr, const float4* __restrict__ wsr,
    const float4* __restrict__ hb)
{
    float a0 = 0.f, a1 = 0.f, a2 = 0.f, a3 = 0.f;
#pragma unroll
    for (int q = 0; q < WREG; q++) {
        float4 h = hb[q];
        float4 w = wr[q];
        a0 = fmaf(w.x, h.x, a0);
        a1 = fmaf(w.y, h.y, a1);
        a2 = fmaf(w.z, h.z, a2);
        a3 = fmaf(w.w, h.w, a3);
    }
#pragma unroll
    for (int q = 0; q < WSMQ; q++) {
        float4 h = hb[WREG + q];
        float4 w = wsr[q];
        a0 = fmaf(w.x, h.x, a0);
        a1 = fmaf(w.y, h.y, a1);
        a2 = fmaf(w.z, h.z, a2);
        a3 = fmaf(w.w, h.w, a3);
    }
    return (a0 + a1) + (a2 + a3);
}

extern __shared__ float smem_r[];

__global__ void __launch_bounds__(256, 1) rnn_recur(
    const float* __restrict__ pre,        // [B][T][D]
    const float* __restrict__ Whh,        // [D][D]
    __nv_bfloat16* __restrict__ houtH,    // [B][T][D]
    __nv_bfloat16* __restrict__ houtL)
{
    float4* Wsm = (float4*)smem_r;
    float*  hA  = smem_r + 256 * WPITCH4 * 4;
    float*  hB  = hA + 256;

    int b = blockIdx.x;
    int j = threadIdx.x;

    float4 wr[WREG];
    {
        const float4* wrow = (const float4*)(Whh + (size_t)j * 256);
#pragma unroll
        for (int q = 0; q < WREG; q++) wr[q] = wrow[q];
    }
    for (int i = j; i < 256 * WSMQ; i += 256) {
        int r = i >> 4, c = i & 15;
        Wsm[r * WPITCH4 + c] =
            ((const float4*)(Whh + (size_t)r * 256 + WREG * 4))[c];
    }

    hA[j] = 0.f;
    __syncthreads();

    const float*   prow = pre   + ((size_t)b * Tn) * Dn;
    __nv_bfloat16* ohr  = houtH + ((size_t)b * Tn) * Dn;
    __nv_bfloat16* olr  = houtL + ((size_t)b * Tn) * Dn;
    const float4*  wsr  = Wsm + j * WPITCH4;

    float pcur = prow[j];

#pragma unroll 1
    for (int step = 0; step < Tn; step += 2) {
        {
            float pnext = prow[Dn + j];
            float s = rnn_dot(wr, wsr, (const float4*)hA);
            float v = tanhf(pcur + s);
            hB[j] = v;
            __nv_bfloat16 vh = __float2bfloat16(v);
            ohr[j] = vh;
            olr[j] = __float2bfloat16(v - __bfloat162float(vh));
            __syncthreads();
            pcur = pnext; prow += Dn; ohr += Dn; olr += Dn;
        }
        {
            float pnext = (step + 2 < Tn) ? prow[Dn + j] : 0.f;
            float s = rnn_dot(wr, wsr, (const float4*)hB);
            float v = tanhf(pcur + s);
            hA[j] = v;
            __nv_bfloat16 vh = __float2bfloat16(v);
            ohr[j] = vh;
            olr[j] = __float2bfloat16(v - __bfloat162float(vh));
            __syncthreads();
            pcur = pnext; prow += Dn; ohr += Dn; olr += Dn;
        }
    }
}

// ---------------------------------------------------------------------------
extern "C" void kernel_launch(void* const* d_in, const int* in_sizes, int n_in,
                              void* d_out, int out_size)
{
    (void)in_sizes; (void)n_in; (void)out_size;

    const int*   ids   = (const int*)  d_in[0];
    const float* emb   = (const float*)d_in[1];
    const float* Wih0  = (const float*)d_in[2];
    const float* Whh0  = (const float*)d_in[3];
    const float* bih0  = (const float*)d_in[4];
    const float* bhh0  = (const float*)d_in[5];
    const float* Wih1  = (const float*)d_in[6];
    const float* Whh1  = (const float*)d_in[7];
    const float* bih1  = (const float*)d_in[8];
    const float* bhh1  = (const float*)d_in[9];
    const float* Whead = (const float*)d_in[10];
    float* out = (float*)d_out;

    float *pre;           cudaGetSymbolAddress((void**)&pre,  g_pre);
    __nv_bfloat16 *hH;    cudaGetSymbolAddress((void**)&hH,   g_hH);
    __nv_bfloat16 *hL;    cudaGetSymbolAddress((void**)&hL,   g_hL);
    __nv_bfloat16 *embH;  cudaGetSymbolAddress((void**)&embH, g_embH);
    __nv_bfloat16 *embL;  cudaGetSymbolAddress((void**)&embL, g_embL);
    __nv_bfloat16 *w0H;   cudaGetSymbolAddress((void**)&w0H,  g_w0H);
    __nv_bfloat16 *w0L;   cudaGetSymbolAddress((void**)&w0L,  g_w0L);
    __nv_bfloat16 *w1H;   cudaGetSymbolAddress((void**)&w1H,  g_w1H);
    __nv_bfloat16 *w1L;   cudaGetSymbolAddress((void**)&w1L,  g_w1L);
    __nv_bfloat16 *whH;   cudaGetSymbolAddress((void**)&whH,  g_whH);
    __nv_bfloat16 *whL;   cudaGetSymbolAddress((void**)&whL,  g_whL);

    const int recur_smem = (256 * WPITCH4 * 4 + 512) * 4;   // 71680 B
    cudaFuncSetAttribute(rnn_recur, cudaFuncAttributeMaxDynamicSharedMemorySize,
                         recur_smem);
    cudaFuncSetAttribute(gemm_mma, cudaFuncAttributeMaxDynamicSharedMemorySize,
                         GEMM_SMEM);

    // All four bf16 hi/lo splits in one launch
    conv_all<<<(SEG3 + 255) / 256, 256>>>(emb, Wih0, Wih1, Whead,
                                          embH, embL, w0H, w0L,
                                          w1H, w1L, whH, whL);

    const int M = Bn * Tn;   // 65536

    // pre0 = emb[ids] @ W_ih0^T + (b_ih0 + b_hh0)
    gemm_mma<<<M / MT, 256, GEMM_SMEM>>>(embH, embL, ids, w0H, w0L,
                                         bih0, bhh0, pre, Dn);
    // h1 recurrence (emits bf16 hi/lo)
    rnn_recur<<<Bn, 256, recur_smem>>>(pre, Whh0, hH, hL);
    // pre1 = h1 @ W_ih1^T + (b_ih1 + b_hh1)
    gemm_mma<<<M / MT, 256, GEMM_SMEM>>>(hH, hL, nullptr, w1H, w1L,
                                         bih1, bhh1, pre, Dn);
    // h2 recurrence
    rnn_recur<<<Bn, 256, recur_smem>>>(pre, Whh1, hH, hL);
    // logits = h2 @ W_head^T
    gemm_mma<<<M / MT, 256, GEMM_SMEM>>>(hH, hL, nullptr, whH, whL,
                                         nullptr, nullptr, out, Sn);
}

// round 16
// speedup vs baseline: 1.1288x; 1.0611x over previous
#include <cuda_runtime.h>
#include <cuda_bf16.h>
#include <math.h>
#include <stdint.h>

#define Bn 128
#define Tn 512
#define Dn 256
#define Vn 4096
#define Sn 512

// ---------------------------------------------------------------------------
// Device scratch (no cudaMalloc allowed)
// ---------------------------------------------------------------------------
__device__ float          g_pre[Bn * Tn * Dn];          // fp32 pre-activations
__device__ __nv_bfloat16  g_hH[Bn * Tn * Dn];           // hidden hi
__device__ __nv_bfloat16  g_hL[Bn * Tn * Dn];           // hidden lo
__device__ __nv_bfloat16  g_embH[Vn * Dn], g_embL[Vn * Dn];
__device__ __nv_bfloat16  g_w0H[Dn * Dn],  g_w0L[Dn * Dn];
__device__ __nv_bfloat16  g_w1H[Dn * Dn],  g_w1L[Dn * Dn];
__device__ __nv_bfloat16  g_whH[Sn * Dn],  g_whL[Sn * Dn];

// ---------------------------------------------------------------------------
// mma.sync / ldmatrix / cp.async helpers (sm_80-era PTX: legal under compute_103)
// ---------------------------------------------------------------------------
__device__ __forceinline__ uint32_t smem_u32(const void* p) {
    uint32_t a;
    asm("{ .reg .u64 t; cvta.to.shared.u64 t, %1; cvt.u32.u64 %0, t; }"
        : "=r"(a) : "l"(p));
    return a;
}
__device__ __forceinline__ void ldsm4(uint32_t r[4], uint32_t addr) {
    asm volatile("ldmatrix.sync.aligned.m8n8.x4.shared.b16 {%0,%1,%2,%3}, [%4];"
                 : "=r"(r[0]), "=r"(r[1]), "=r"(r[2]), "=r"(r[3]) : "r"(addr));
}
__device__ __forceinline__ void mma_bf16(float d[4], const uint32_t a[4],
                                         const uint32_t b[2]) {
    asm volatile(
        "mma.sync.aligned.m16n8k16.row.col.f32.bf16.bf16.f32 "
        "{%0,%1,%2,%3}, {%4,%5,%6,%7}, {%8,%9}, {%0,%1,%2,%3};"
        : "+f"(d[0]), "+f"(d[1]), "+f"(d[2]), "+f"(d[3])
        : "r"(a[0]), "r"(a[1]), "r"(a[2]), "r"(a[3]), "r"(b[0]), "r"(b[1]));
}
__device__ __forceinline__ void cpa16(uint32_t saddr, const void* g) {
    asm volatile("cp.async.cg.shared.global [%0], [%1], 16;"
                 :: "r"(saddr), "l"(g) : "memory");
}
#define CPA_COMMIT() asm volatile("cp.async.commit_group;" ::: "memory")
#define CPA_WAIT1()  asm volatile("cp.async.wait_group 1;" ::: "memory")

// ---------------------------------------------------------------------------
// Tensor-core GEMM, MT=64, WARP-PRIVATE B pipeline (zero CTA barriers in the
// K-loop): 8 warps = 1(m) x 8(n); warp w owns B cols [16w,16w+16) exclusively,
// loads them with its own cp.async groups, syncs with wait_group + syncwarp.
// A tile CTA-shared, read-only after ONE initial __syncthreads.
// smem 108544 B -> 2 CTAs/SM (16 warps) keep the tensor pipe covered.
// C[M][N] = (AH+AL)[M][256] * (BH+BL)[N][256]^T (+b1[n]+b2[n])
// ---------------------------------------------------------------------------
#define MT      64
#define A_PITCH 528
#define B_PITCH 80
#define SM_AH   0
#define SM_AL   (MT * A_PITCH)                 // 33792
#define SM_B    (2 * MT * A_PITCH)             // 67584
#define B_SEG   (128 * B_PITCH)                // 10240
#define GEMM_SMEM (SM_B + 2 * 2 * B_SEG)       // 108544 B -> 2 CTAs/SM

__global__ __launch_bounds__(256) void gemm_mma(
    const __nv_bfloat16* __restrict__ AH, const __nv_bfloat16* __restrict__ AL,
    const int* __restrict__ ids,
    const __nv_bfloat16* __restrict__ BH, const __nv_bfloat16* __restrict__ BL,
    const float* __restrict__ b1, const float* __restrict__ b2,
    float* __restrict__ C, int N)
{
    extern __shared__ char gsm[];
    const uint32_t sb = smem_u32(gsm);

    const int tid = threadIdx.x;
    const int wid = tid >> 5, lane = tid & 31;
    const int m0 = blockIdx.x * MT;

    // ---- A tile (64 x 256, hi+lo) via cp.async; cross-warp, one barrier ----
#pragma unroll 4
    for (int i = tid; i < 2048; i += 256) {
        int row = i >> 5, seg = i & 31;
        int src = ids ? __ldg(ids + m0 + row) : (m0 + row);
        cpa16(sb + SM_AH + row * A_PITCH + seg * 16,
              AH + (size_t)src * 256 + seg * 8);
        cpa16(sb + SM_AL + row * A_PITCH + seg * 16,
              AL + (size_t)src * 256 + seg * 8);
    }
    CPA_COMMIT();

    // ---- Per-lane ldmatrix addresses ----
    // A: all 64 rows read by every warp (i = 0..3 m16 tiles)
    const uint32_t aOff = (uint32_t)(lane & 15) * A_PITCH + ((lane >> 4) * 8) * 2;
    const uint32_t aBaseH = sb + SM_AH + aOff;
    const uint32_t aBaseL = sb + SM_AL + aOff;
    // B: warp-private 16 rows [16*wid, 16*wid+16)
    const int bN = wid * 16 + (lane & 7) + ((lane >> 4) << 3);
    const uint32_t bOff = (uint32_t)bN * B_PITCH + ((lane >> 3) & 1) * 16;

    // ---- Warp-private B loader: lane -> row 16*wid + (lane>>1), 32B half ----
    const int lrow = wid * 16 + (lane >> 1);
    const int lcolE = (lane & 1) * 16;          // element offset (16 bf16 = 32B)
    const uint32_t bstW = sb + SM_B + lrow * B_PITCH + lcolE * 2;

    bool firstSync = true;

    const int nTiles = N >> 7;
#pragma unroll 1
    for (int nt = 0; nt < nTiles; nt++) {
        const int n0 = nt << 7;

        float acc[4][2][4];
#pragma unroll
        for (int i = 0; i < 4; i++)
#pragma unroll
            for (int j = 0; j < 2; j++)
#pragma unroll
                for (int r = 0; r < 4; r++) acc[i][j][r] = 0.f;

        // prologue: stages 0 and 1 (warp-private, one commit group each)
#pragma unroll
        for (int pc = 0; pc < 2; pc++) {
            const __nv_bfloat16* gh =
                BH + (size_t)(n0 + lrow) * 256 + pc * 32 + lcolE;
            const __nv_bfloat16* gl =
                BL + (size_t)(n0 + lrow) * 256 + pc * 32 + lcolE;
            uint32_t d = bstW + pc * (2 * B_SEG);
            cpa16(d, gh);             cpa16(d + 16, gh + 8);
            cpa16(d + B_SEG, gl);     cpa16(d + B_SEG + 16, gl + 8);
            CPA_COMMIT();
        }

#pragma unroll 1
        for (int kc = 0; kc < 8; kc++) {
            CPA_WAIT1();            // stage kc complete (this thread's copies)
            if (firstSync) {        // once: A visible CTA-wide
                __syncthreads();
                firstSync = false;
            } else {
                __syncwarp();       // warp-private B visible across the warp
            }

            const uint32_t hiB = sb + SM_B + (uint32_t)(kc & 1) * (2 * B_SEG) + bOff;
            const uint32_t loB = hiB + B_SEG;

            // MMA over this chunk (two k16 steps)
#pragma unroll
            for (int kk = 0; kk < 2; kk++) {
                const uint32_t aK = (uint32_t)(kc * 2 + kk) * 32;
                uint32_t aH[4][4], aL[4][4];
#pragma unroll
                for (int i = 0; i < 4; i++) {
                    ldsm4(aH[i], aBaseH + i * (16 * A_PITCH) + aK);
                    ldsm4(aL[i], aBaseL + i * (16 * A_PITCH) + aK);
                }
                uint32_t bH[4], bL[4];
                ldsm4(bH, hiB + (uint32_t)kk * 32);
                ldsm4(bL, loB + (uint32_t)kk * 32);
#pragma unroll
                for (int i = 0; i < 4; i++)
#pragma unroll
                    for (int j = 0; j < 2; j++)
                        mma_bf16(acc[i][j], aH[i], &bH[j * 2]);
#pragma unroll
                for (int i = 0; i < 4; i++)
#pragma unroll
                    for (int j = 0; j < 2; j++)
                        mma_bf16(acc[i][j], aH[i], &bL[j * 2]);
#pragma unroll
                for (int i = 0; i < 4; i++)
#pragma unroll
                    for (int j = 0; j < 2; j++)
                        mma_bf16(acc[i][j], aL[i], &bH[j * 2]);
            }

            __syncwarp();           // warp's reads of slot kc&1 complete

            // refill slot kc&1 with stage kc+2 (empty commit when drained)
            if (kc < 6) {
                const __nv_bfloat16* gh =
                    BH + (size_t)(n0 + lrow) * 256 + (kc + 2) * 32 + lcolE;
                const __nv_bfloat16* gl =
                    BL + (size_t)(n0 + lrow) * 256 + (kc + 2) * 32 + lcolE;
                uint32_t d = bstW + (uint32_t)(kc & 1) * (2 * B_SEG);
                cpa16(d, gh);             cpa16(d + 16, gh + 8);
                cpa16(d + B_SEG, gl);     cpa16(d + B_SEG + 16, gl + 8);
            }
            CPA_COMMIT();
        }

        // ---- Epilogue: add bias, store fp32 C (warp-independent) ----
        const int rBase = m0 + (lane >> 2);
        const int cBase = n0 + wid * 16 + (lane & 3) * 2;
#pragma unroll
        for (int j = 0; j < 2; j++) {
            const int col = cBase + j * 8;
            float bb0 = 0.f, bb1 = 0.f;
            if (b1) {
                bb0 = b1[col] + b2[col];
                bb1 = b1[col + 1] + b2[col + 1];
            }
#pragma unroll
            for (int i = 0; i < 4; i++) {
                const int row = rBase + i * 16;
                float2 v0 = make_float2(acc[i][j][0] + bb0, acc[i][j][1] + bb1);
                float2 v1 = make_float2(acc[i][j][2] + bb0, acc[i][j][3] + bb1);
                *(float2*)(C + (size_t)row * N + col) = v0;
                *(float2*)(C + (size_t)(row + 8) * N + col) = v1;
            }
        }
    }
}

// ---------------------------------------------------------------------------
// fp32 -> bf16 hi/lo split: ALL four tables in one launch
// ---------------------------------------------------------------------------
#define SEG0 (Vn * Dn)              // 1048576
#define SEG1 (SEG0 + Dn * Dn)       // 1114112
#define SEG2 (SEG1 + Dn * Dn)       // 1179648
#define SEG3 (SEG2 + Sn * Dn)       // 1310720

__global__ void conv_all(
    const float* __restrict__ emb, const float* __restrict__ w0,
    const float* __restrict__ w1,  const float* __restrict__ wh,
    __nv_bfloat16* __restrict__ embH, __nv_bfloat16* __restrict__ embL,
    __nv_bfloat16* __restrict__ w0H,  __nv_bfloat16* __restrict__ w0L,
    __nv_bfloat16* __restrict__ w1H,  __nv_bfloat16* __restrict__ w1L,
    __nv_bfloat16* __restrict__ whH,  __nv_bfloat16* __restrict__ whL)
{
    int i = blockIdx.x * 256 + threadIdx.x;
    if (i >= SEG3) return;
    const float* src;
    __nv_bfloat16 *hi, *lo;
    int k;
    if (i < SEG0)      { src = emb; hi = embH; lo = embL; k = i; }
    else if (i < SEG1) { src = w0;  hi = w0H;  lo = w0L;  k = i - SEG0; }
    else if (i < SEG2) { src = w1;  hi = w1H;  lo = w1L;  k = i - SEG1; }
    else               { src = wh;  hi = whH;  lo = whL;  k = i - SEG2; }
    float v = src[k];
    __nv_bfloat16 h = __float2bfloat16(v);
    hi[k] = h;
    lo[k] = __float2bfloat16(v - __bfloat162float(h));
}

// ---------------------------------------------------------------------------
// Recurrence (round-4 champion, byte-identical — empirically optimal after
// 7 alternative designs all regressed): one CTA per batch row, 512 steps.
//   h_t = tanh(pre_t + W_hh @ h_{t-1})
// Thread j owns output row j: W[j][0:192] in 48 float4 registers,
// W[:][192:256] via smem pitch-17-float4; h double-buffered, 1 barrier/step.
// Emits h as bf16 hi/lo for the GEMM A-operand.
// ---------------------------------------------------------------------------
#define WREG 48
#define WSMQ 16
#define WPITCH4 17

__device__ __forceinline__ float rnn_dot(
    const float4* __restrict__ wr, const float4* __restrict__ wsr,
    const float4* __restrict__ hb)
{
    float a0 = 0.f, a1 = 0.f, a2 = 0.f, a3 = 0.f;
#pragma unroll
    for (int q = 0; q < WREG; q++) {
        float4 h = hb[q];
        float4 w = wr[q];
        a0 = fmaf(w.x, h.x, a0);
        a1 = fmaf(w.y, h.y, a1);
        a2 = fmaf(w.z, h.z, a2);
        a3 = fmaf(w.w, h.w, a3);
    }
#pragma unroll
    for (int q = 0; q < WSMQ; q++) {
        float4 h = hb[WREG + q];
        float4 w = wsr[q];
        a0 = fmaf(w.x, h.x, a0);
        a1 = fmaf(w.y, h.y, a1);
        a2 = fmaf(w.z, h.z, a2);
        a3 = fmaf(w.w, h.w, a3);
    }
    return (a0 + a1) + (a2 + a3);
}

extern __shared__ float smem_r[];

__global__ void __launch_bounds__(256, 1) rnn_recur(
    const float* __restrict__ pre,        // [B][T][D]
    const float* __restrict__ Whh,        // [D][D]
    __nv_bfloat16* __restrict__ houtH,    // [B][T][D]
    __nv_bfloat16* __restrict__ houtL)
{
    float4* Wsm = (float4*)smem_r;
    float*  hA  = smem_r + 256 * WPITCH4 * 4;
    float*  hB  = hA + 256;

    int b = blockIdx.x;
    int j = threadIdx.x;

    float4 wr[WREG];
    {
        const float4* wrow = (const float4*)(Whh + (size_t)j * 256);
#pragma unroll
        for (int q = 0; q < WREG; q++) wr[q] = wrow[q];
    }
    for (int i = j; i < 256 * WSMQ; i += 256) {
        int r = i >> 4, c = i & 15;
        Wsm[r * WPITCH4 + c] =
            ((const float4*)(Whh + (size_t)r * 256 + WREG * 4))[c];
    }

    hA[j] = 0.f;
    __syncthreads();

    const float*   prow = pre   + ((size_t)b * Tn) * Dn;
    __nv_bfloat16* ohr  = houtH + ((size_t)b * Tn) * Dn;
    __nv_bfloat16* olr  = houtL + ((size_t)b * Tn) * Dn;
    const float4*  wsr  = Wsm + j * WPITCH4;

    float pcur = prow[j];

#pragma unroll 1
    for (int step = 0; step < Tn; step += 2) {
        {
            float pnext = prow[Dn + j];
            float s = rnn_dot(wr, wsr, (const float4*)hA);
            float v = tanhf(pcur + s);
            hB[j] = v;
            __nv_bfloat16 vh = __float2bfloat16(v);
            ohr[j] = vh;
            olr[j] = __float2bfloat16(v - __bfloat162float(vh));
            __syncthreads();
            pcur = pnext; prow += Dn; ohr += Dn; olr += Dn;
        }
        {
            float pnext = (step + 2 < Tn) ? prow[Dn + j] : 0.f;
            float s = rnn_dot(wr, wsr, (const float4*)hB);
            float v = tanhf(pcur + s);
            hA[j] = v;
            __nv_bfloat16 vh = __float2bfloat16(v);
            ohr[j] = vh;
            olr[j] = __float2bfloat16(v - __bfloat162float(vh));
            __syncthreads();
            pcur = pnext; prow += Dn; ohr += Dn; olr += Dn;
        }
    }
}

// ---------------------------------------------------------------------------
extern "C" void kernel_launch(void* const* d_in, const int* in_sizes, int n_in,
                              void* d_out, int out_size)
{
    (void)in_sizes; (void)n_in; (void)out_size;

    const int*   ids   = (const int*)  d_in[0];
    const float* emb   = (const float*)d_in[1];
    const float* Wih0  = (const float*)d_in[2];
    const float* Whh0  = (const float*)d_in[3];
    const float* bih0  = (const float*)d_in[4];
    const float* bhh0  = (const float*)d_in[5];
    const float* Wih1  = (const float*)d_in[6];
    const float* Whh1  = (const float*)d_in[7];
    const float* bih1  = (const float*)d_in[8];
    const float* bhh1  = (const float*)d_in[9];
    const float* Whead = (const float*)d_in[10];
    float* out = (float*)d_out;

    float *pre;           cudaGetSymbolAddress((void**)&pre,  g_pre);
    __nv_bfloat16 *hH;    cudaGetSymbolAddress((void**)&hH,   g_hH);
    __nv_bfloat16 *hL;    cudaGetSymbolAddress((void**)&hL,   g_hL);
    __nv_bfloat16 *embH;  cudaGetSymbolAddress((void**)&embH, g_embH);
    __nv_bfloat16 *embL;  cudaGetSymbolAddress((void**)&embL, g_embL);
    __nv_bfloat16 *w0H;   cudaGetSymbolAddress((void**)&w0H,  g_w0H);
    __nv_bfloat16 *w0L;   cudaGetSymbolAddress((void**)&w0L,  g_w0L);
    __nv_bfloat16 *w1H;   cudaGetSymbolAddress((void**)&w1H,  g_w1H);
    __nv_bfloat16 *w1L;   cudaGetSymbolAddress((void**)&w1L,  g_w1L);
    __nv_bfloat16 *whH;   cudaGetSymbolAddress((void**)&whH,  g_whH);
    __nv_bfloat16 *whL;   cudaGetSymbolAddress((void**)&whL,  g_whL);

    const int recur_smem = (256 * WPITCH4 * 4 + 512) * 4;   // 71680 B
    cudaFuncSetAttribute(rnn_recur, cudaFuncAttributeMaxDynamicSharedMemorySize,
                         recur_smem);
    cudaFuncSetAttribute(gemm_mma, cudaFuncAttributeMaxDynamicSharedMemorySize,
                         GEMM_SMEM);

    // All four bf16 hi/lo splits in one launch
    conv_all<<<(SEG3 + 255) / 256, 256>>>(emb, Wih0, Wih1, Whead,
                                          embH, embL, w0H, w0L,
                                          w1H, w1L, whH, whL);

    const int M = Bn * Tn;   // 65536

    // pre0 = emb[ids] @ W_ih0^T + (b_ih0 + b_hh0)
    gemm_mma<<<M / MT, 256, GEMM_SMEM>>>(embH, embL, ids, w0H, w0L,
                                         bih0, bhh0, pre, Dn);
    // h1 recurrence (emits bf16 hi/lo)
    rnn_recur<<<Bn, 256, recur_smem>>>(pre, Whh0, hH, hL);
    // pre1 = h1 @ W_ih1^T + (b_ih1 + b_hh1)
    gemm_mma<<<M / MT, 256, GEMM_SMEM>>>(hH, hL, nullptr, w1H, w1L,
                                         bih1, bhh1, pre, Dn);
    // h2 recurrence
    rnn_recur<<<Bn, 256, recur_smem>>>(pre, Whh1, hH, hL);
    // logits = h2 @ W_head^T
    gemm_mma<<<M / MT, 256, GEMM_SMEM>>>(hH, hL, nullptr, whH, whL,
                                         nullptr, nullptr, out, Sn);
}

// round 17
// speedup vs baseline: 1.1381x; 1.0083x over previous
#include <cuda_runtime.h>
#include <cuda_bf16.h>
#include <math.h>
#include <stdint.h>

#define Bn 128
#define Tn 512
#define Dn 256
#define Vn 4096
#define Sn 512

// ---------------------------------------------------------------------------
// Device scratch (no cudaMalloc allowed)
// ---------------------------------------------------------------------------
__device__ float          g_pre[Bn * Tn * Dn];          // fp32 pre-activations
__device__ __nv_bfloat16  g_hH[Bn * Tn * Dn];           // hidden hi
__device__ __nv_bfloat16  g_hL[Bn * Tn * Dn];           // hidden lo
__device__ __nv_bfloat16  g_embH[Vn * Dn], g_embL[Vn * Dn];
__device__ __nv_bfloat16  g_w0H[Dn * Dn],  g_w0L[Dn * Dn];
__device__ __nv_bfloat16  g_w1H[Dn * Dn],  g_w1L[Dn * Dn];
__device__ __nv_bfloat16  g_whH[Sn * Dn],  g_whL[Sn * Dn];

// ---------------------------------------------------------------------------
// mma.sync / ldmatrix / cp.async helpers (sm_80-era PTX: legal under compute_103)
// ---------------------------------------------------------------------------
__device__ __forceinline__ uint32_t smem_u32(const void* p) {
    uint32_t a;
    asm("{ .reg .u64 t; cvta.to.shared.u64 t, %1; cvt.u32.u64 %0, t; }"
        : "=r"(a) : "l"(p));
    return a;
}
__device__ __forceinline__ void ldsm4(uint32_t r[4], uint32_t addr) {
    asm volatile("ldmatrix.sync.aligned.m8n8.x4.shared.b16 {%0,%1,%2,%3}, [%4];"
                 : "=r"(r[0]), "=r"(r[1]), "=r"(r[2]), "=r"(r[3]) : "r"(addr));
}
__device__ __forceinline__ void mma_bf16(float d[4], const uint32_t a[4],
                                         const uint32_t b[2]) {
    asm volatile(
        "mma.sync.aligned.m16n8k16.row.col.f32.bf16.bf16.f32 "
        "{%0,%1,%2,%3}, {%4,%5,%6,%7}, {%8,%9}, {%0,%1,%2,%3};"
        : "+f"(d[0]), "+f"(d[1]), "+f"(d[2]), "+f"(d[3])
        : "r"(a[0]), "r"(a[1]), "r"(a[2]), "r"(a[3]), "r"(b[0]), "r"(b[1]));
}
__device__ __forceinline__ void cpa16(uint32_t saddr, const void* g) {
    asm volatile("cp.async.cg.shared.global [%0], [%1], 16;"
                 :: "r"(saddr), "l"(g) : "memory");
}
#define CPA_COMMIT() asm volatile("cp.async.commit_group;" ::: "memory")
#define CPA_WAIT1()  asm volatile("cp.async.wait_group 1;" ::: "memory")

// ---------------------------------------------------------------------------
// Tensor-core GEMM, MT=64, warp-private B pipeline, v2 micro-pass:
//  - single __syncwarp per K-chunk (post-wait). The pre-refill syncwarp is
//    redundant: LDSM results feed MMAs via register scoreboards, so every
//    lane's smem reads complete before its MMAs issue; the warp is converged,
//    so all cp.async refills issue strictly after all MMAs -> no smem race.
//  - kc loop fully unrolled: static slot addressing, static refill predicate.
// 8 warps = 1(m) x 8(n); warp w owns B cols [16w,16w+16) exclusively.
// smem 108544 B -> 2 CTAs/SM. C = (AH+AL)(BH+BL)^T (3-product bf16 split;
// 2-product fails: dropped A-lo term alone is ~1.1e-3 relative error).
// ---------------------------------------------------------------------------
#define MT      64
#define A_PITCH 528
#define B_PITCH 80
#define SM_AH   0
#define SM_AL   (MT * A_PITCH)                 // 33792
#define SM_B    (2 * MT * A_PITCH)             // 67584
#define B_SEG   (128 * B_PITCH)                // 10240
#define GEMM_SMEM (SM_B + 2 * 2 * B_SEG)       // 108544 B -> 2 CTAs/SM

__global__ __launch_bounds__(256) void gemm_mma(
    const __nv_bfloat16* __restrict__ AH, const __nv_bfloat16* __restrict__ AL,
    const int* __restrict__ ids,
    const __nv_bfloat16* __restrict__ BH, const __nv_bfloat16* __restrict__ BL,
    const float* __restrict__ b1, const float* __restrict__ b2,
    float* __restrict__ C, int N)
{
    extern __shared__ char gsm[];
    const uint32_t sb = smem_u32(gsm);

    const int tid = threadIdx.x;
    const int wid = tid >> 5, lane = tid & 31;
    const int m0 = blockIdx.x * MT;

    // ---- A tile (64 x 256, hi+lo) via cp.async; cross-warp, one barrier ----
#pragma unroll 4
    for (int i = tid; i < 2048; i += 256) {
        int row = i >> 5, seg = i & 31;
        int src = ids ? __ldg(ids + m0 + row) : (m0 + row);
        cpa16(sb + SM_AH + row * A_PITCH + seg * 16,
              AH + (size_t)src * 256 + seg * 8);
        cpa16(sb + SM_AL + row * A_PITCH + seg * 16,
              AL + (size_t)src * 256 + seg * 8);
    }
    CPA_COMMIT();

    // ---- Per-lane ldmatrix addresses ----
    const uint32_t aOff = (uint32_t)(lane & 15) * A_PITCH + ((lane >> 4) * 8) * 2;
    const uint32_t aBaseH = sb + SM_AH + aOff;
    const uint32_t aBaseL = sb + SM_AL + aOff;
    const int bN = wid * 16 + (lane & 7) + ((lane >> 4) << 3);
    const uint32_t bOff = (uint32_t)bN * B_PITCH + ((lane >> 3) & 1) * 16;

    // ---- Warp-private B loader: lane -> row 16*wid + (lane>>1), 32B half ----
    const int lrow = wid * 16 + (lane >> 1);
    const int lcolE = (lane & 1) * 16;          // element offset (16 bf16 = 32B)
    const uint32_t bstW = sb + SM_B + lrow * B_PITCH + lcolE * 2;

    bool firstSync = true;

    const int nTiles = N >> 7;
#pragma unroll 1
    for (int nt = 0; nt < nTiles; nt++) {
        const int n0 = nt << 7;

        float acc[4][2][4];
#pragma unroll
        for (int i = 0; i < 4; i++)
#pragma unroll
            for (int j = 0; j < 2; j++)
#pragma unroll
                for (int r = 0; r < 4; r++) acc[i][j][r] = 0.f;

        // prologue: stages 0 and 1 (warp-private, one commit group each)
#pragma unroll
        for (int pc = 0; pc < 2; pc++) {
            const __nv_bfloat16* gh =
                BH + (size_t)(n0 + lrow) * 256 + pc * 32 + lcolE;
            const __nv_bfloat16* gl =
                BL + (size_t)(n0 + lrow) * 256 + pc * 32 + lcolE;
            uint32_t d = bstW + pc * (2 * B_SEG);
            cpa16(d, gh);             cpa16(d + 16, gh + 8);
            cpa16(d + B_SEG, gl);     cpa16(d + B_SEG + 16, gl + 8);
            CPA_COMMIT();
        }

#pragma unroll
        for (int kc = 0; kc < 8; kc++) {
            CPA_WAIT1();            // stage kc complete (this thread's copies)
            if (firstSync) {        // once per kernel: A visible CTA-wide
                __syncthreads();
                firstSync = false;
            } else {
                __syncwarp();       // warp-private B visible across the warp
            }

            const uint32_t hiB = sb + SM_B + (uint32_t)(kc & 1) * (2 * B_SEG) + bOff;
            const uint32_t loB = hiB + B_SEG;

            // MMA over this chunk (two k16 steps)
#pragma unroll
            for (int kk = 0; kk < 2; kk++) {
                const uint32_t aK = (uint32_t)(kc * 2 + kk) * 32;
                uint32_t aH[4][4], aL[4][4];
#pragma unroll
                for (int i = 0; i < 4; i++) {
                    ldsm4(aH[i], aBaseH + i * (16 * A_PITCH) + aK);
                    ldsm4(aL[i], aBaseL + i * (16 * A_PITCH) + aK);
                }
                uint32_t bH[4], bL[4];
                ldsm4(bH, hiB + (uint32_t)kk * 32);
                ldsm4(bL, loB + (uint32_t)kk * 32);
#pragma unroll
                for (int i = 0; i < 4; i++)
#pragma unroll
                    for (int j = 0; j < 2; j++)
                        mma_bf16(acc[i][j], aH[i], &bH[j * 2]);
#pragma unroll
                for (int i = 0; i < 4; i++)
#pragma unroll
                    for (int j = 0; j < 2; j++)
                        mma_bf16(acc[i][j], aH[i], &bL[j * 2]);
#pragma unroll
                for (int i = 0; i < 4; i++)
#pragma unroll
                    for (int j = 0; j < 2; j++)
                        mma_bf16(acc[i][j], aL[i], &bH[j * 2]);
            }

            // refill slot kc&1 with stage kc+2 (no syncwarp needed: all lanes'
            // LDSM reads completed before their MMAs issued, and the warp is
            // converged, so these cp.async issue after every lane's reads)
            if (kc < 6) {
                const __nv_bfloat16* gh =
                    BH + (size_t)(n0 + lrow) * 256 + (kc + 2) * 32 + lcolE;
                const __nv_bfloat16* gl =
                    BL + (size_t)(n0 + lrow) * 256 + (kc + 2) * 32 + lcolE;
                uint32_t d = bstW + (uint32_t)(kc & 1) * (2 * B_SEG);
                cpa16(d, gh);             cpa16(d + 16, gh + 8);
                cpa16(d + B_SEG, gl);     cpa16(d + B_SEG + 16, gl + 8);
            }
            CPA_COMMIT();           // empty group when drained (uniform count)
        }

        // ---- Epilogue: add bias, store fp32 C (warp-independent) ----
        const int rBase = m0 + (lane >> 2);
        const int cBase = n0 + wid * 16 + (lane & 3) * 2;
#pragma unroll
        for (int j = 0; j < 2; j++) {
            const int col = cBase + j * 8;
            float bb0 = 0.f, bb1 = 0.f;
            if (b1) {
                bb0 = b1[col] + b2[col];
                bb1 = b1[col + 1] + b2[col + 1];
            }
#pragma unroll
            for (int i = 0; i < 4; i++) {
                const int row = rBase + i * 16;
                float2 v0 = make_float2(acc[i][j][0] + bb0, acc[i][j][1] + bb1);
                float2 v1 = make_float2(acc[i][j][2] + bb0, acc[i][j][3] + bb1);
                *(float2*)(C + (size_t)row * N + col) = v0;
                *(float2*)(C + (size_t)(row + 8) * N + col) = v1;
            }
        }
    }
}

// ---------------------------------------------------------------------------
// fp32 -> bf16 hi/lo split: ALL four tables in one launch
// ---------------------------------------------------------------------------
#define SEG0 (Vn * Dn)              // 1048576
#define SEG1 (SEG0 + Dn * Dn)       // 1114112
#define SEG2 (SEG1 + Dn * Dn)       // 1179648
#define SEG3 (SEG2 + Sn * Dn)       // 1310720

__global__ void conv_all(
    const float* __restrict__ emb, const float* __restrict__ w0,
    const float* __restrict__ w1,  const float* __restrict__ wh,
    __nv_bfloat16* __restrict__ embH, __nv_bfloat16* __restrict__ embL,
    __nv_bfloat16* __restrict__ w0H,  __nv_bfloat16* __restrict__ w0L,
    __nv_bfloat16* __restrict__ w1H,  __nv_bfloat16* __restrict__ w1L,
    __nv_bfloat16* __restrict__ whH,  __nv_bfloat16* __restrict__ whL)
{
    int i = blockIdx.x * 256 + threadIdx.x;
    if (i >= SEG3) return;
    const float* src;
    __nv_bfloat16 *hi, *lo;
    int k;
    if (i < SEG0)      { src = emb; hi = embH; lo = embL; k = i; }
    else if (i < SEG1) { src = w0;  hi = w0H;  lo = w0L;  k = i - SEG0; }
    else if (i < SEG2) { src = w1;  hi = w1H;  lo = w1L;  k = i - SEG1; }
    else               { src = wh;  hi = whH;  lo = whL;  k = i - SEG2; }
    float v = src[k];
    __nv_bfloat16 h = __float2bfloat16(v);
    hi[k] = h;
    lo[k] = __float2bfloat16(v - __bfloat162float(h));
}

// ---------------------------------------------------------------------------
// Recurrence (round-4 champion, byte-identical — empirically optimal after
// 7 alternative designs all regressed): one CTA per batch row, 512 steps.
//   h_t = tanh(pre_t + W_hh @ h_{t-1})
// Thread j owns output row j: W[j][0:192] in 48 float4 registers,
// W[:][192:256] via smem pitch-17-float4; h double-buffered, 1 barrier/step.
// Emits h as bf16 hi/lo for the GEMM A-operand.
// ---------------------------------------------------------------------------
#define WREG 48
#define WSMQ 16
#define WPITCH4 17

__device__ __forceinline__ float rnn_dot(
    const float4* __restrict__ wr, const float4* __restrict__ wsr,
    const float4* __restrict__ hb)
{
    float a0 = 0.f, a1 = 0.f, a2 = 0.f, a3 = 0.f;
#pragma unroll
    for (int q = 0; q < WREG; q++) {
        float4 h = hb[q];
        float4 w = wr[q];
        a0 = fmaf(w.x, h.x, a0);
        a1 = fmaf(w.y, h.y, a1);
        a2 = fmaf(w.z, h.z, a2);
        a3 = fmaf(w.w, h.w, a3);
    }
#pragma unroll
    for (int q = 0; q < WSMQ; q++) {
        float4 h = hb[WREG + q];
        float4 w = wsr[q];
        a0 = fmaf(w.x, h.x, a0);
        a1 = fmaf(w.y, h.y, a1);
        a2 = fmaf(w.z, h.z, a2);
        a3 = fmaf(w.w, h.w, a3);
    }
    return (a0 + a1) + (a2 + a3);
}

extern __shared__ float smem_r[];

__global__ void __launch_bounds__(256, 1) rnn_recur(
    const float* __restrict__ pre,        // [B][T][D]
    const float* __restrict__ Whh,        // [D][D]
    __nv_bfloat16* __restrict__ houtH,    // [B][T][D]
    __nv_bfloat16* __restrict__ houtL)
{
    float4* Wsm = (float4*)smem_r;
    float*  hA  = smem_r + 256 * WPITCH4 * 4;
    float*  hB  = hA + 256;

    int b = blockIdx.x;
    int j = threadIdx.x;

    float4 wr[WREG];
    {
        const float4* wrow = (const float4*)(Whh + (size_t)j * 256);
#pragma unroll
        for (int q = 0; q < WREG; q++) wr[q] = wrow[q];
    }
    for (int i = j; i < 256 * WSMQ; i += 256) {
        int r = i >> 4, c = i & 15;
        Wsm[r * WPITCH4 + c] =
            ((const float4*)(Whh + (size_t)r * 256 + WREG * 4))[c];
    }

    hA[j] = 0.f;
    __syncthreads();

    const float*   prow = pre   + ((size_t)b * Tn) * Dn;
    __nv_bfloat16* ohr  = houtH + ((size_t)b * Tn) * Dn;
    __nv_bfloat16* olr  = houtL + ((size_t)b * Tn) * Dn;
    const float4*  wsr  = Wsm + j * WPITCH4;

    float pcur = prow[j];

#pragma unroll 1
    for (int step = 0; step < Tn; step += 2) {
        {
            float pnext = prow[Dn + j];
            float s = rnn_dot(wr, wsr, (const float4*)hA);
            float v = tanhf(pcur + s);
            hB[j] = v;
            __nv_bfloat16 vh = __float2bfloat16(v);
            ohr[j] = vh;
            olr[j] = __float2bfloat16(v - __bfloat162float(vh));
            __syncthreads();
            pcur = pnext; prow += Dn; ohr += Dn; olr += Dn;
        }
        {
            float pnext = (step + 2 < Tn) ? prow[Dn + j] : 0.f;
            float s = rnn_dot(wr, wsr, (const float4*)hB);
            float v = tanhf(pcur + s);
            hA[j] = v;
            __nv_bfloat16 vh = __float2bfloat16(v);
            ohr[j] = vh;
            olr[j] = __float2bfloat16(v - __bfloat162float(vh));
            __syncthreads();
            pcur = pnext; prow += Dn; ohr += Dn; olr += Dn;
        }
    }
}

// ---------------------------------------------------------------------------
extern "C" void kernel_launch(void* const* d_in, const int* in_sizes, int n_in,
                              void* d_out, int out_size)
{
    (void)in_sizes; (void)n_in; (void)out_size;

    const int*   ids   = (const int*)  d_in[0];
    const float* emb   = (const float*)d_in[1];
    const float* Wih0  = (const float*)d_in[2];
    const float* Whh0  = (const float*)d_in[3];
    const float* bih0  = (const float*)d_in[4];
    const float* bhh0  = (const float*)d_in[5];
    const float* Wih1  = (const float*)d_in[6];
    const float* Whh1  = (const float*)d_in[7];
    const float* bih1  = (const float*)d_in[8];
    const float* bhh1  = (const float*)d_in[9];
    const float* Whead = (const float*)d_in[10];
    float* out = (float*)d_out;

    float *pre;           cudaGetSymbolAddress((void**)&pre,  g_pre);
    __nv_bfloat16 *hH;    cudaGetSymbolAddress((void**)&hH,   g_hH);
    __nv_bfloat16 *hL;    cudaGetSymbolAddress((void**)&hL,   g_hL);
    __nv_bfloat16 *embH;  cudaGetSymbolAddress((void**)&embH, g_embH);
    __nv_bfloat16 *embL;  cudaGetSymbolAddress((void**)&embL, g_embL);
    __nv_bfloat16 *w0H;   cudaGetSymbolAddress((void**)&w0H,  g_w0H);
    __nv_bfloat16 *w0L;   cudaGetSymbolAddress((void**)&w0L,  g_w0L);
    __nv_bfloat16 *w1H;   cudaGetSymbolAddress((void**)&w1H,  g_w1H);
    __nv_bfloat16 *w1L;   cudaGetSymbolAddress((void**)&w1L,  g_w1L);
    __nv_bfloat16 *whH;   cudaGetSymbolAddress((void**)&whH,  g_whH);
    __nv_bfloat16 *whL;   cudaGetSymbolAddress((void**)&whL,  g_whL);

    const int recur_smem = (256 * WPITCH4 * 4 + 512) * 4;   // 71680 B
    cudaFuncSetAttribute(rnn_recur, cudaFuncAttributeMaxDynamicSharedMemorySize,
                         recur_smem);
    cudaFuncSetAttribute(gemm_mma, cudaFuncAttributeMaxDynamicSharedMemorySize,
                         GEMM_SMEM);

    // All four bf16 hi/lo splits in one launch
    conv_all<<<(SEG3 + 255) / 256, 256>>>(emb, Wih0, Wih1, Whead,
                                          embH, embL, w0H, w0L,
                                          w1H, w1L, whH, whL);

    const int M = Bn * Tn;   // 65536

    // pre0 = emb[ids] @ W_ih0^T + (b_ih0 + b_hh0)
    gemm_mma<<<M / MT, 256, GEMM_SMEM>>>(embH, embL, ids, w0H, w0L,
                                         bih0, bhh0, pre, Dn);
    // h1 recurrence (emits bf16 hi/lo)
    rnn_recur<<<Bn, 256, recur_smem>>>(pre, Whh0, hH, hL);
    // pre1 = h1 @ W_ih1^T + (b_ih1 + b_hh1)
    gemm_mma<<<M / MT, 256, GEMM_SMEM>>>(hH, hL, nullptr, w1H, w1L,
                                         bih1, bhh1, pre, Dn);
    // h2 recurrence
    rnn_recur<<<Bn, 256, recur_smem>>>(pre, Whh1, hH, hL);
    // logits = h2 @ W_head^T
    gemm_mma<<<M / MT, 256, GEMM_SMEM>>>(hH, hL, nullptr, whH, whL,
                                         nullptr, nullptr, out, Sn);
}